// round 11
// baseline (speedup 1.0000x reference)
#include <cuda_runtime.h>
#include <cuda_fp16.h>

#define FM_H 38
#define FM_W 50
#define N_ROI 512
#define POOL 7
#define FM_ELEMS (FM_H * FM_W * 512)

// fp16 copy of the feature map (static scratch; allocation-free).
__device__ __align__(16) static __half g_fmh[FM_ELEMS];

// ---- fp32 -> fp16 convert kernel ----
__global__ __launch_bounds__(256) void convert_kernel(const float* __restrict__ fm) {
    const int i = blockIdx.x * blockDim.x + threadIdx.x;   // one float4 each
    const int n4 = FM_ELEMS / 4;
    if (i < n4) {
        const float4 v = ((const float4*)fm)[i];
        __half2 h0 = __floats2half2_rn(v.x, v.y);
        __half2 h1 = __floats2half2_rn(v.z, v.w);
        uint2 u;
        u.x = *reinterpret_cast<unsigned*>(&h0);
        u.y = *reinterpret_cast<unsigned*>(&h1);
        ((uint2*)g_fmh)[i] = u;
    }
}

// ---- half8 helpers (one LDG.128 per tap) ----
struct h8 { __half2 h[4]; };

__device__ __forceinline__ h8 ld_h8(const uint4* __restrict__ p) {
    const uint4 u = *p;                    // single LDG.128
    h8 v;
    v.h[0] = *reinterpret_cast<const __half2*>(&u.x);
    v.h[1] = *reinterpret_cast<const __half2*>(&u.y);
    v.h[2] = *reinterpret_cast<const __half2*>(&u.z);
    v.h[3] = *reinterpret_cast<const __half2*>(&u.w);
    return v;
}

__device__ __forceinline__ h8 quad8h(h8 A, h8 B, h8 C, h8 D,
                                     __half2 w0, __half2 w1, __half2 w2, __half2 w3) {
    h8 r;
#pragma unroll
    for (int i = 0; i < 4; ++i)
        r.h[i] = __hfma2(D.h[i], w3, __hfma2(C.h[i], w2,
                 __hfma2(B.h[i], w1, __hmul2(A.h[i], w0))));
    return r;
}

__device__ __forceinline__ h8 max8h(h8 x, h8 y) {
    h8 r;
#pragma unroll
    for (int i = 0; i < 4; ++i) r.h[i] = __hmax2(x.h[i], y.h[i]);
    return r;
}

// MODE 0: 2 distinct fm rows; pair-b reuses them via folded row weights.
// MODE 1: 3 rows, pair-b reads (r1,r2). MODE 2: 4 rows, pair-b reads (r2,r3).
// Each cell split into two column-pair halves to cap live registers:
//   load cols (x0a,x1a) across NR rows -> points aa/ba,
//   load cols (x0b,x1b) across NR rows -> points ab/bb.
// Straight-line across all 7 cells; all loads unconditional.
template <int MODE>
__device__ __forceinline__ void run_row(
    const uint4* __restrict__ fmt, float4* __restrict__ outp,
    float x1n, float dx,
    int r0, int r1, int r2, int r3,
    __half2 hwaP, __half2 hwaQ,    // row weights pair a (rows r0,r1)
    __half2 hwbP, __half2 hwbQ,    // row weights pair b (rows per MODE)
    int t)
{
    constexpr int NR = (MODE == 0) ? 2 : (MODE == 1) ? 3 : 4;
    constexpr int PB = (MODE == 0) ? 0 : (MODE == 1) ? 1 : 2;
    int ro[4] = {r0, r1, r2, r3};

#pragma unroll
    for (int px = 0; px < POOL; ++px) {
        // x taps for the two crop cols of this pooled cell (block-uniform)
        int x0a, x1a, x0b, x1b;
        float wxa, wxb;
        {
            const float txa = (float)(2 * px) * (1.0f / 13.0f);
            const float xsa = (x1n + txa * dx) * (float)(FM_W - 1);
            const float xfa = floorf(xsa);
            int x0 = (int)xfa; x0 = min(max(x0, 0), FM_W - 1);
            x0a = x0; x1a = min(x0 + 1, FM_W - 1); wxa = xsa - xfa;

            const float txb = (float)(2 * px + 1) * (1.0f / 13.0f);
            const float xsb = (x1n + txb * dx) * (float)(FM_W - 1);
            const float xfb = floorf(xsb);
            int x1 = (int)xfb; x1 = min(max(x1, 0), FM_W - 1);
            x0b = x1; x1b = min(x1 + 1, FM_W - 1); wxb = xsb - xfb;
        }
        const __half2 huxa = __float2half2_rn(1.0f - wxa);
        const __half2 hwxa = __float2half2_rn(wxa);
        const __half2 huxb = __float2half2_rn(1.0f - wxb);
        const __half2 hwxb = __float2half2_rn(wxb);

        // ---- half 1: column pair a ----
        h8 s_aa, s_ba;
        {
            h8 C0[NR], C1[NR];
#pragma unroll
            for (int r = 0; r < NR; ++r) {
                C0[r] = ld_h8(fmt + (ro[r] + x0a) * 64);
                C1[r] = ld_h8(fmt + (ro[r] + x1a) * 64);
            }
            s_aa = quad8h(C0[0], C1[0], C0[1], C1[1],
                          __hmul2(hwaP, huxa), __hmul2(hwaP, hwxa),
                          __hmul2(hwaQ, huxa), __hmul2(hwaQ, hwxa));
            s_ba = quad8h(C0[PB], C1[PB], C0[PB + 1], C1[PB + 1],
                          __hmul2(hwbP, huxa), __hmul2(hwbP, hwxa),
                          __hmul2(hwbQ, huxa), __hmul2(hwbQ, hwxa));
        }

        // ---- half 2: column pair b ----
        h8 s_ab, s_bb;
        {
            h8 C0[NR], C1[NR];
#pragma unroll
            for (int r = 0; r < NR; ++r) {
                C0[r] = ld_h8(fmt + (ro[r] + x0b) * 64);
                C1[r] = ld_h8(fmt + (ro[r] + x1b) * 64);
            }
            s_ab = quad8h(C0[0], C1[0], C0[1], C1[1],
                          __hmul2(hwaP, huxb), __hmul2(hwaP, hwxb),
                          __hmul2(hwaQ, huxb), __hmul2(hwaQ, hwxb));
            s_bb = quad8h(C0[PB], C1[PB], C0[PB + 1], C1[PB + 1],
                          __hmul2(hwbP, huxb), __hmul2(hwbP, hwxb),
                          __hmul2(hwbQ, huxb), __hmul2(hwbQ, hwxb));
        }

        const h8 m = max8h(max8h(s_aa, s_ab), max8h(s_ba, s_bb));

        // 8 fp32 outputs per thread: two contiguous float4 stores
        float4* op = outp + px * 128 + 2 * t;
        const float2 f0 = __half22float2(m.h[0]);
        const float2 f1 = __half22float2(m.h[1]);
        const float2 f2 = __half22float2(m.h[2]);
        const float2 f3 = __half22float2(m.h[3]);
        op[0] = make_float4(f0.x, f0.y, f1.x, f1.y);
        op[1] = make_float4(f2.x, f2.y, f3.x, f3.y);
    }
}

// One block per (pooled_row, roi). 64 threads x half8 = 512 channels.
// Row-tap dedup via ONE block-uniform dispatch; cell loop branch-free.
__global__ __launch_bounds__(64) void roi_pool_kernel(
    const float* __restrict__ rois,   // [512,5] (0, x1, y1, x2, y2)
    float* __restrict__ out)          // [512,7,7,512]
{
    const int py  = blockIdx.x;       // 0..6
    const int roi = blockIdx.y;       // 0..511
    const int t   = threadIdx.x;      // channel group: c = 8*t

    const float* r = rois + roi * 5;
    const float x1n = r[1] * (1.0f / 800.0f);
    const float y1n = r[2] * (1.0f / 600.0f);
    const float x2n = r[3] * (1.0f / 800.0f);
    const float y2n = r[4] * (1.0f / 600.0f);
    const float dy = y2n - y1n;
    const float dx = x2n - x1n;

    // y taps for the two crop rows of this pooled row (block-uniform)
    int ra0, ra1, rb0, rb1;           // fm row offsets (row * FM_W)
    float wya, wyb;
    {
        const float tya = (float)(2 * py) * (1.0f / 13.0f);
        const float ysa = (y1n + tya * dy) * (float)(FM_H - 1);
        const float yfa = floorf(ysa);
        int y0 = (int)yfa; y0 = min(max(y0, 0), FM_H - 1);
        ra0 = y0 * FM_W;
        ra1 = min(y0 + 1, FM_H - 1) * FM_W;
        wya = ysa - yfa;

        const float tyb = (float)(2 * py + 1) * (1.0f / 13.0f);
        const float ysb = (y1n + tyb * dy) * (float)(FM_H - 1);
        const float yfb = floorf(ysb);
        int y1 = (int)yfb; y1 = min(max(y1, 0), FM_H - 1);
        rb0 = y1 * FM_W;
        rb1 = min(y1 + 1, FM_H - 1) * FM_W;
        wyb = ysb - yfb;
    }

    const uint4* fmt = (const uint4*)g_fmh + t;
    float4* outp = (float4*)out + (size_t)((roi * POOL + py) * POOL) * 128;

    const __half2 hwya = __float2half2_rn(wya);
    const __half2 huya = __float2half2_rn(1.0f - wya);
    const __half2 hwyb = __float2half2_rn(wyb);
    const __half2 huyb = __float2half2_rn(1.0f - wyb);

    // Row dedup dispatch (block-uniform branch, fixed for all 7 cells).
    if (rb0 == ra0) {
        run_row<0>(fmt, outp, x1n, dx, ra0, ra1, 0, 0,
                   huya, hwya, huyb, hwyb, t);
    } else if (rb0 == ra1) {
        if (rb1 == rb0) {
            run_row<0>(fmt, outp, x1n, dx, ra0, ra1, 0, 0,
                       huya, hwya, __float2half2_rn(0.0f), __float2half2_rn(1.0f), t);
        } else {
            run_row<1>(fmt, outp, x1n, dx, ra0, ra1, rb1, 0,
                       huya, hwya, huyb, hwyb, t);
        }
    } else {
        run_row<2>(fmt, outp, x1n, dx, ra0, ra1, rb0, rb1,
                   huya, hwya, huyb, hwyb, t);
    }
}

extern "C" void kernel_launch(void* const* d_in, const int* in_sizes, int n_in,
                              void* d_out, int out_size)
{
    const float* fm   = (const float*)d_in[0];   // feature_maps [1,38,50,512]
    const float* rois = (const float*)d_in[1];   // [512,5]
    float* out = (float*)d_out;                  // [1,512,7,7,512]

    const int n4 = FM_ELEMS / 4;
    convert_kernel<<<(n4 + 255) / 256, 256>>>(fm);

    dim3 grid(POOL, N_ROI);
    roi_pool_kernel<<<grid, 64>>>(rois, out);
}

// round 12
// speedup vs baseline: 1.4759x; 1.4759x over previous
#include <cuda_runtime.h>
#include <cuda_fp16.h>

#define FM_H 38
#define FM_W 50
#define N_ROI 512
#define POOL 7
#define FM_ELEMS (FM_H * FM_W * 512)
#define N_CELLS (N_ROI * POOL * POOL)      // 25088
#define N_ROWBLK (N_ROI * POOL)            // 3584
#define N4 (FM_ELEMS / 4)                  // 243200
#define N4BLOCKS (N4 / 256)                // 950

// Static scratch (allocation-free).
__device__ __align__(16) static __half g_fmh[FM_ELEMS];   // fp16 feature map
__device__ static int4  g_cols[N_CELLS];       // premult col offsets (x*128)
__device__ static uint4 g_w[N_CELLS * 2];      // 16 half2 weight products
__device__ static int4  g_rows[N_ROWBLK];      // premult row offsets (y*50*128)
__device__ static int   g_mode[N_ROWBLK];      // row-dedup mode 0/1/2

__device__ __forceinline__ unsigned pack_h2(float f) {
    __half2 h = __float2half2_rn(f);
    return *reinterpret_cast<unsigned*>(&h);
}

// ---- combined fp32->fp16 convert + per-cell parameter precompute ----
__global__ __launch_bounds__(256) void prep_kernel(
    const float* __restrict__ fm, const float* __restrict__ rois)
{
    const int b = blockIdx.x;
    if (b < N4BLOCKS) {
        const int i = b * 256 + threadIdx.x;      // one float4 each
        const float4 v = ((const float4*)fm)[i];
        __half2 h0 = __floats2half2_rn(v.x, v.y);
        __half2 h1 = __floats2half2_rn(v.z, v.w);
        uint2 u;
        u.x = *reinterpret_cast<unsigned*>(&h0);
        u.y = *reinterpret_cast<unsigned*>(&h1);
        ((uint2*)g_fmh)[i] = u;
        return;
    }
    const int idx = (b - N4BLOCKS) * 256 + threadIdx.x;   // cell id
    if (idx >= N_CELLS) return;
    const int roi = idx / (POOL * POOL);
    const int rem = idx - roi * POOL * POOL;
    const int py  = rem / POOL;
    const int px  = rem - py * POOL;

    const float* r = rois + roi * 5;
    const float x1n = r[1] * (1.0f / 800.0f);
    const float y1n = r[2] * (1.0f / 600.0f);
    const float x2n = r[3] * (1.0f / 800.0f);
    const float y2n = r[4] * (1.0f / 600.0f);
    const float dy = y2n - y1n;
    const float dx = x2n - x1n;

    // y taps for this pooled row
    int ya0, ya1, yb0, yb1;
    float wya, wyb;
    {
        const float tya = (float)(2 * py) * (1.0f / 13.0f);
        const float ysa = (y1n + tya * dy) * (float)(FM_H - 1);
        const float yfa = floorf(ysa);
        int y0 = (int)yfa; y0 = min(max(y0, 0), FM_H - 1);
        ya0 = y0; ya1 = min(y0 + 1, FM_H - 1); wya = ysa - yfa;

        const float tyb = (float)(2 * py + 1) * (1.0f / 13.0f);
        const float ysb = (y1n + tyb * dy) * (float)(FM_H - 1);
        const float yfb = floorf(ysb);
        int y1 = (int)yfb; y1 = min(max(y1, 0), FM_H - 1);
        yb0 = y1; yb1 = min(y1 + 1, FM_H - 1); wyb = ysb - yfb;
    }
    const float uya = 1.0f - wya;
    const float uyb = 1.0f - wyb;

    // Row-dedup mode + folded pair-b row weights + row set
    int mode, r0 = ya0, r1 = ya1, r2 = 0, r3 = 0;
    float waP = uya, waQ = wya, wbP, wbQ;
    if (yb0 == ya0) {
        mode = 0; wbP = uyb; wbQ = wyb;
    } else if (yb0 == ya1) {
        if (yb1 == yb0) { mode = 0; wbP = 0.0f; wbQ = uyb + wyb; }
        else { mode = 1; r2 = yb1; wbP = uyb; wbQ = wyb; }
    } else {
        mode = 2; r2 = yb0; r3 = yb1; wbP = uyb; wbQ = wyb;
    }
    if (px == 0) {
        const int rb = roi * POOL + py;
        g_rows[rb] = make_int4(r0 * (FM_W * 128), r1 * (FM_W * 128),
                               r2 * (FM_W * 128), r3 * (FM_W * 128));
        g_mode[rb] = mode;
    }

    // x taps for this pooled cell
    int x0a, x1a, x0b, x1b;
    float wxa, wxb;
    {
        const float txa = (float)(2 * px) * (1.0f / 13.0f);
        const float xsa = (x1n + txa * dx) * (float)(FM_W - 1);
        const float xfa = floorf(xsa);
        int x0 = (int)xfa; x0 = min(max(x0, 0), FM_W - 1);
        x0a = x0; x1a = min(x0 + 1, FM_W - 1); wxa = xsa - xfa;

        const float txb = (float)(2 * px + 1) * (1.0f / 13.0f);
        const float xsb = (x1n + txb * dx) * (float)(FM_W - 1);
        const float xfb = floorf(xsb);
        int x1 = (int)xfb; x1 = min(max(x1, 0), FM_W - 1);
        x0b = x1; x1b = min(x1 + 1, FM_W - 1); wxb = xsb - xfb;
    }
    const float uxa = 1.0f - wxa;
    const float uxb = 1.0f - wxb;

    g_cols[idx] = make_int4(x0a * 128, x1a * 128, x0b * 128, x1b * 128);

    // 16 weight products (fp32 mult, single round to half2)
    uint4 wA, wB;
    wA.x = pack_h2(waP * uxa);  wA.y = pack_h2(waP * wxa);
    wA.z = pack_h2(waQ * uxa);  wA.w = pack_h2(waQ * wxa);
    uint4 wA2;
    wA2.x = pack_h2(waP * uxb); wA2.y = pack_h2(waP * wxb);
    wA2.z = pack_h2(waQ * uxb); wA2.w = pack_h2(waQ * wxb);
    wB.x = pack_h2(wbP * uxa);  wB.y = pack_h2(wbP * wxa);
    wB.z = pack_h2(wbQ * uxa);  wB.w = pack_h2(wbQ * wxa);
    uint4 wB2;
    wB2.x = pack_h2(wbP * uxb); wB2.y = pack_h2(wbP * wxb);
    wB2.z = pack_h2(wbQ * uxb); wB2.w = pack_h2(wbQ * wxb);
    // layout: [aa(4), ab(4)] in g_w[2*idx], [ba(4), bb(4)] in g_w[2*idx+1]
    // -> store as two uint4 pairs: first = {aa, ab} needs 8 -> use two uint4
    g_w[2 * idx]     = make_uint4(wA.x, wA.y, wA.z, wA.w);
    g_w[2 * idx + 1] = make_uint4(wB.x, wB.y, wB.z, wB.w);
    // second pair stored interleaved in the same arrays? -> need 4 uint4 total.
    // Repack: use g_w2 arrays below.
    ((uint4*)g_cols)[0] = ((uint4*)g_cols)[0];   // no-op keep compiler quiet
    // NOTE: ab/bb products stored in g_wb
    extern __device__ uint4 g_wb[];              // fwd decl trick not allowed; see real array
    (void)wA2; (void)wB2;
}

// Real storage for the b-column weight products (ab, bb quads).
__device__ static uint4 g_wab[N_CELLS];   // ab products
__device__ static uint4 g_wbb[N_CELLS];   // bb products

__global__ __launch_bounds__(256) void prep_fix_kernel(
    const float* __restrict__ rois)
{
    const int idx = blockIdx.x * 256 + threadIdx.x;
    if (idx >= N_CELLS) return;
    const int roi = idx / (POOL * POOL);
    const int rem = idx - roi * POOL * POOL;
    const int py  = rem / POOL;
    const int px  = rem - py * POOL;

    const float* r = rois + roi * 5;
    const float x1n = r[1] * (1.0f / 800.0f);
    const float y1n = r[2] * (1.0f / 600.0f);
    const float x2n = r[3] * (1.0f / 800.0f);
    const float y2n = r[4] * (1.0f / 600.0f);
    const float dy = y2n - y1n;
    const float dx = x2n - x1n;

    int ya0, ya1, yb0, yb1;
    float wya, wyb;
    {
        const float tya = (float)(2 * py) * (1.0f / 13.0f);
        const float ysa = (y1n + tya * dy) * (float)(FM_H - 1);
        const float yfa = floorf(ysa);
        int y0 = (int)yfa; y0 = min(max(y0, 0), FM_H - 1);
        ya0 = y0; ya1 = min(y0 + 1, FM_H - 1); wya = ysa - yfa;

        const float tyb = (float)(2 * py + 1) * (1.0f / 13.0f);
        const float ysb = (y1n + tyb * dy) * (float)(FM_H - 1);
        const float yfb = floorf(ysb);
        int y1 = (int)yfb; y1 = min(max(y1, 0), FM_H - 1);
        yb0 = y1; yb1 = min(y1 + 1, FM_H - 1); wyb = ysb - yfb;
    }
    const float uya = 1.0f - wya;
    const float uyb = 1.0f - wyb;

    float waP = uya, waQ = wya, wbP, wbQ;
    if (yb0 == ya0) { wbP = uyb; wbQ = wyb; }
    else if (yb0 == ya1) {
        if (yb1 == yb0) { wbP = 0.0f; wbQ = uyb + wyb; }
        else { wbP = uyb; wbQ = wyb; }
    } else { wbP = uyb; wbQ = wyb; }

    float wxb;
    {
        const float txb = (float)(2 * px + 1) * (1.0f / 13.0f);
        const float xsb = (x1n + txb * dx) * (float)(FM_W - 1);
        wxb = xsb - floorf(xsb);
    }
    const float uxb = 1.0f - wxb;

    g_wab[idx] = make_uint4(pack_h2(waP * uxb), pack_h2(waP * wxb),
                            pack_h2(waQ * uxb), pack_h2(waQ * wxb));
    g_wbb[idx] = make_uint4(pack_h2(wbP * uxb), pack_h2(wbP * wxb),
                            pack_h2(wbQ * uxb), pack_h2(wbQ * wxb));
}

// ---- half4 helpers ----
struct h4 { __half2 a, b; };

__device__ __forceinline__ h4 ld_h4(const uint2* __restrict__ p) {
    const uint2 u = *p;                    // single LDG.64
    h4 v;
    v.a = *reinterpret_cast<const __half2*>(&u.x);
    v.b = *reinterpret_cast<const __half2*>(&u.y);
    return v;
}

__device__ __forceinline__ __half2 as_h2(unsigned u) {
    return *reinterpret_cast<__half2*>(&u);
}

__device__ __forceinline__ h4 quad4h(h4 A, h4 B, h4 C, h4 D,
                                     __half2 w0, __half2 w1, __half2 w2, __half2 w3) {
    h4 r;
    r.a = __hfma2(D.a, w3, __hfma2(C.a, w2, __hfma2(B.a, w1, __hmul2(A.a, w0))));
    r.b = __hfma2(D.b, w3, __hfma2(C.b, w2, __hfma2(B.b, w1, __hmul2(A.b, w0))));
    return r;
}

__device__ __forceinline__ h4 max4h(h4 x, h4 y) {
    h4 r;
    r.a = __hmax2(x.a, y.a);
    r.b = __hmax2(x.b, y.b);
    return r;
}

// MODE 0: rows (r0,r1) for both point pairs. MODE 1: pair-b on (r1,r2).
// MODE 2: pair-b on (r2,r3). Straight-line across 7 cells, all loads
// unconditional; all setup comes from precomputed params (uniform loads).
template <int MODE>
__device__ __forceinline__ void run_row(
    const uint2* __restrict__ fmt, float4* __restrict__ outp,
    const int4* __restrict__ colsp,
    const uint4* __restrict__ wq, const uint4* __restrict__ wab,
    const uint4* __restrict__ wbb, int4 rows)
{
#pragma unroll
    for (int px = 0; px < POOL; ++px) {
        const int4  c   = colsp[px];
        const uint4 wAa = wq[2 * px];        // aa products
        const uint4 wBa = wq[2 * px + 1];    // ba products
        const uint4 wAb = wab[px];           // ab products
        const uint4 wBb = wbb[px];           // bb products

        const h4 vA0a = ld_h4(fmt + (rows.x + c.x));
        const h4 vA1a = ld_h4(fmt + (rows.x + c.y));
        const h4 vA0b = ld_h4(fmt + (rows.x + c.z));
        const h4 vA1b = ld_h4(fmt + (rows.x + c.w));
        const h4 vB0a = ld_h4(fmt + (rows.y + c.x));
        const h4 vB1a = ld_h4(fmt + (rows.y + c.y));
        const h4 vB0b = ld_h4(fmt + (rows.y + c.z));
        const h4 vB1b = ld_h4(fmt + (rows.y + c.w));

        h4 vC0a, vC1a, vC0b, vC1b, vD0a, vD1a, vD0b, vD1b;
        if (MODE == 0) {
            vC0a = vA0a; vC1a = vA1a; vC0b = vA0b; vC1b = vA1b;
            vD0a = vB0a; vD1a = vB1a; vD0b = vB0b; vD1b = vB1b;
        } else if (MODE == 1) {
            vC0a = vB0a; vC1a = vB1a; vC0b = vB0b; vC1b = vB1b;
            vD0a = ld_h4(fmt + (rows.z + c.x));
            vD1a = ld_h4(fmt + (rows.z + c.y));
            vD0b = ld_h4(fmt + (rows.z + c.z));
            vD1b = ld_h4(fmt + (rows.z + c.w));
        } else {
            vC0a = ld_h4(fmt + (rows.z + c.x));
            vC1a = ld_h4(fmt + (rows.z + c.y));
            vC0b = ld_h4(fmt + (rows.z + c.z));
            vC1b = ld_h4(fmt + (rows.z + c.w));
            vD0a = ld_h4(fmt + (rows.w + c.x));
            vD1a = ld_h4(fmt + (rows.w + c.y));
            vD0b = ld_h4(fmt + (rows.w + c.z));
            vD1b = ld_h4(fmt + (rows.w + c.w));
        }

        const h4 s_aa = quad4h(vA0a, vA1a, vB0a, vB1a,
                               as_h2(wAa.x), as_h2(wAa.y), as_h2(wAa.z), as_h2(wAa.w));
        const h4 s_ab = quad4h(vA0b, vA1b, vB0b, vB1b,
                               as_h2(wAb.x), as_h2(wAb.y), as_h2(wAb.z), as_h2(wAb.w));
        const h4 s_ba = quad4h(vC0a, vC1a, vD0a, vD1a,
                               as_h2(wBa.x), as_h2(wBa.y), as_h2(wBa.z), as_h2(wBa.w));
        const h4 s_bb = quad4h(vC0b, vC1b, vD0b, vD1b,
                               as_h2(wBb.x), as_h2(wBb.y), as_h2(wBb.z), as_h2(wBb.w));

        const h4 m = max4h(max4h(s_aa, s_ab), max4h(s_ba, s_bb));
        const float2 lo = __half22float2(m.a);
        const float2 hi = __half22float2(m.b);
        outp[px * 128] = make_float4(lo.x, lo.y, hi.x, hi.y);
    }
}

// One block per (pooled_row, roi). 128 threads x half4 = 512 channels.
__global__ __launch_bounds__(128) void roi_pool_kernel(
    float* __restrict__ out)          // [512,7,7,512]
{
    const int py  = blockIdx.x;       // 0..6
    const int roi = blockIdx.y;       // 0..511
    const int t   = threadIdx.x;      // channel group: c = 4*t

    const int rb   = roi * POOL + py;
    const int cb   = rb * POOL;
    const int4 rows = g_rows[rb];
    const int mode  = g_mode[rb];

    const uint2* fmt = (const uint2*)g_fmh + t;
    float4* outp = (float4*)out + (size_t)cb * 128 + t;

    const int4*  colsp = g_cols + cb;
    const uint4* wq    = g_w + 2 * cb;
    const uint4* wab   = g_wab + cb;
    const uint4* wbb   = g_wbb + cb;

    if (mode == 0)      run_row<0>(fmt, outp, colsp, wq, wab, wbb, rows);
    else if (mode == 1) run_row<1>(fmt, outp, colsp, wq, wab, wbb, rows);
    else                run_row<2>(fmt, outp, colsp, wq, wab, wbb, rows);
}

extern "C" void kernel_launch(void* const* d_in, const int* in_sizes, int n_in,
                              void* d_out, int out_size)
{
    const float* fm   = (const float*)d_in[0];   // feature_maps [1,38,50,512]
    const float* rois = (const float*)d_in[1];   // [512,5]
    float* out = (float*)d_out;                  // [1,512,7,7,512]

    const int param_blocks = (N_CELLS + 255) / 256;          // 98
    prep_kernel<<<N4BLOCKS + param_blocks, 256>>>(fm, rois);
    prep_fix_kernel<<<param_blocks, 256>>>(rois);

    dim3 grid(POOL, N_ROI);
    roi_pool_kernel<<<grid, 128>>>(out);
}

// round 13
// speedup vs baseline: 1.4906x; 1.0100x over previous
#include <cuda_runtime.h>
#include <cuda_fp16.h>

#define FM_H 38
#define FM_W 50
#define N_ROI 512
#define POOL 7
#define FM_ELEMS (FM_H * FM_W * 512)
#define N_CELLS (N_ROI * POOL * POOL)      // 25088
#define N_ROWBLK (N_ROI * POOL)            // 3584
#define N8 (FM_ELEMS / 8)                  // 121600 (two float4 per thread)
#define N8BLOCKS ((N8 + 255) / 256)        // 475

// Static scratch (allocation-free).
__device__ __align__(16) static __half g_fmh[FM_ELEMS];   // fp16 feature map
__device__ static int4  g_cols[N_CELLS];       // premult col offsets (x*128)
__device__ static uint4 g_waa[N_CELLS];        // weight quads per point
__device__ static uint4 g_wab[N_CELLS];
__device__ static uint4 g_wba[N_CELLS];
__device__ static uint4 g_wbb[N_CELLS];
__device__ static int4  g_rows[N_ROWBLK];      // premult row offsets (y*50*128)
__device__ static int   g_mode[N_ROWBLK];      // row-dedup mode 0/1/2

__device__ __forceinline__ unsigned pack_h2(float f) {
    __half2 h = __float2half2_rn(f);
    return *reinterpret_cast<unsigned*>(&h);
}

// ---- merged fp32->fp16 convert + per-cell parameter precompute ----
__global__ __launch_bounds__(256) void prep_kernel(
    const float* __restrict__ fm, const float* __restrict__ rois)
{
    const int b = blockIdx.x;
    if (b < N8BLOCKS) {
        // convert: 2 independent float4 -> uint2 per thread (MLP=2)
        const int i = (b * 256 + threadIdx.x) * 2;
        const float4 v0 = ((const float4*)fm)[i];
        const float4 v1 = ((const float4*)fm)[i + 1];
        __half2 a0 = __floats2half2_rn(v0.x, v0.y);
        __half2 a1 = __floats2half2_rn(v0.z, v0.w);
        __half2 b0 = __floats2half2_rn(v1.x, v1.y);
        __half2 b1 = __floats2half2_rn(v1.z, v1.w);
        uint4 u;
        u.x = *reinterpret_cast<unsigned*>(&a0);
        u.y = *reinterpret_cast<unsigned*>(&a1);
        u.z = *reinterpret_cast<unsigned*>(&b0);
        u.w = *reinterpret_cast<unsigned*>(&b1);
        ((uint4*)g_fmh)[i >> 1] = u;
        return;
    }
    const int idx = (b - N8BLOCKS) * 256 + threadIdx.x;   // cell id
    if (idx >= N_CELLS) return;
    const int roi = idx / (POOL * POOL);
    const int rem = idx - roi * POOL * POOL;
    const int py  = rem / POOL;
    const int px  = rem - py * POOL;

    const float* r = rois + roi * 5;
    const float x1n = r[1] * (1.0f / 800.0f);
    const float y1n = r[2] * (1.0f / 600.0f);
    const float x2n = r[3] * (1.0f / 800.0f);
    const float y2n = r[4] * (1.0f / 600.0f);
    const float dy = y2n - y1n;
    const float dx = x2n - x1n;

    // y taps for this pooled row
    int ya0, ya1, yb0, yb1;
    float wya, wyb;
    {
        const float tya = (float)(2 * py) * (1.0f / 13.0f);
        const float ysa = (y1n + tya * dy) * (float)(FM_H - 1);
        const float yfa = floorf(ysa);
        int y0 = (int)yfa; y0 = min(max(y0, 0), FM_H - 1);
        ya0 = y0; ya1 = min(y0 + 1, FM_H - 1); wya = ysa - yfa;

        const float tyb = (float)(2 * py + 1) * (1.0f / 13.0f);
        const float ysb = (y1n + tyb * dy) * (float)(FM_H - 1);
        const float yfb = floorf(ysb);
        int y1 = (int)yfb; y1 = min(max(y1, 0), FM_H - 1);
        yb0 = y1; yb1 = min(y1 + 1, FM_H - 1); wyb = ysb - yfb;
    }
    const float uya = 1.0f - wya;
    const float uyb = 1.0f - wyb;

    // Row-dedup mode + folded pair-b row weights + row set
    int mode, r2 = 0, r3 = 0;
    float waP = uya, waQ = wya, wbP, wbQ;
    if (yb0 == ya0) {
        mode = 0; wbP = uyb; wbQ = wyb;
    } else if (yb0 == ya1) {
        if (yb1 == yb0) { mode = 0; wbP = 0.0f; wbQ = uyb + wyb; }
        else { mode = 1; r2 = yb1; wbP = uyb; wbQ = wyb; }
    } else {
        mode = 2; r2 = yb0; r3 = yb1; wbP = uyb; wbQ = wyb;
    }
    if (px == 0) {
        const int rb = roi * POOL + py;
        g_rows[rb] = make_int4(ya0 * (FM_W * 128), ya1 * (FM_W * 128),
                               r2 * (FM_W * 128), r3 * (FM_W * 128));
        g_mode[rb] = mode;
    }

    // x taps for this pooled cell
    int x0a, x1a, x0b, x1b;
    float wxa, wxb;
    {
        const float txa = (float)(2 * px) * (1.0f / 13.0f);
        const float xsa = (x1n + txa * dx) * (float)(FM_W - 1);
        const float xfa = floorf(xsa);
        int x0 = (int)xfa; x0 = min(max(x0, 0), FM_W - 1);
        x0a = x0; x1a = min(x0 + 1, FM_W - 1); wxa = xsa - xfa;

        const float txb = (float)(2 * px + 1) * (1.0f / 13.0f);
        const float xsb = (x1n + txb * dx) * (float)(FM_W - 1);
        const float xfb = floorf(xsb);
        int x1 = (int)xfb; x1 = min(max(x1, 0), FM_W - 1);
        x0b = x1; x1b = min(x1 + 1, FM_W - 1); wxb = xsb - xfb;
    }
    const float uxa = 1.0f - wxa;
    const float uxb = 1.0f - wxb;

    g_cols[idx] = make_int4(x0a * 128, x1a * 128, x0b * 128, x1b * 128);

    // 16 weight products (fp32 mult, single round to half2)
    g_waa[idx] = make_uint4(pack_h2(waP * uxa), pack_h2(waP * wxa),
                            pack_h2(waQ * uxa), pack_h2(waQ * wxa));
    g_wab[idx] = make_uint4(pack_h2(waP * uxb), pack_h2(waP * wxb),
                            pack_h2(waQ * uxb), pack_h2(waQ * wxb));
    g_wba[idx] = make_uint4(pack_h2(wbP * uxa), pack_h2(wbP * wxa),
                            pack_h2(wbQ * uxa), pack_h2(wbQ * wxa));
    g_wbb[idx] = make_uint4(pack_h2(wbP * uxb), pack_h2(wbP * wxb),
                            pack_h2(wbQ * uxb), pack_h2(wbQ * wxb));
}

// ---- half4 helpers ----
struct h4 { __half2 a, b; };

__device__ __forceinline__ h4 ld_h4(const uint2* __restrict__ p) {
    const uint2 u = *p;                    // single LDG.64
    h4 v;
    v.a = *reinterpret_cast<const __half2*>(&u.x);
    v.b = *reinterpret_cast<const __half2*>(&u.y);
    return v;
}

__device__ __forceinline__ __half2 as_h2(unsigned u) {
    return *reinterpret_cast<__half2*>(&u);
}

__device__ __forceinline__ h4 quad4h(h4 A, h4 B, h4 C, h4 D,
                                     __half2 w0, __half2 w1, __half2 w2, __half2 w3) {
    h4 r;
    r.a = __hfma2(D.a, w3, __hfma2(C.a, w2, __hfma2(B.a, w1, __hmul2(A.a, w0))));
    r.b = __hfma2(D.b, w3, __hfma2(C.b, w2, __hfma2(B.b, w1, __hmul2(A.b, w0))));
    return r;
}

__device__ __forceinline__ h4 max4h(h4 x, h4 y) {
    h4 r;
    r.a = __hmax2(x.a, y.a);
    r.b = __hmax2(x.b, y.b);
    return r;
}

// MODE 0: rows (r0,r1) for both point pairs. MODE 1: pair-b on (r1,r2).
// MODE 2: pair-b on (r2,r3). Straight-line across 7 cells, all loads
// unconditional; all setup comes from precomputed params (uniform loads).
template <int MODE>
__device__ __forceinline__ void run_row(
    const uint2* __restrict__ fmt, float4* __restrict__ outp,
    const int4* __restrict__ colsp,
    const uint4* __restrict__ waa, const uint4* __restrict__ wab,
    const uint4* __restrict__ wba, const uint4* __restrict__ wbb,
    int4 rows)
{
#pragma unroll
    for (int px = 0; px < POOL; ++px) {
        const int4  c   = colsp[px];
        const uint4 wAa = waa[px];
        const uint4 wAb = wab[px];
        const uint4 wBa = wba[px];
        const uint4 wBb = wbb[px];

        const h4 vA0a = ld_h4(fmt + (rows.x + c.x));
        const h4 vA1a = ld_h4(fmt + (rows.x + c.y));
        const h4 vA0b = ld_h4(fmt + (rows.x + c.z));
        const h4 vA1b = ld_h4(fmt + (rows.x + c.w));
        const h4 vB0a = ld_h4(fmt + (rows.y + c.x));
        const h4 vB1a = ld_h4(fmt + (rows.y + c.y));
        const h4 vB0b = ld_h4(fmt + (rows.y + c.z));
        const h4 vB1b = ld_h4(fmt + (rows.y + c.w));

        h4 vC0a, vC1a, vC0b, vC1b, vD0a, vD1a, vD0b, vD1b;
        if (MODE == 0) {
            vC0a = vA0a; vC1a = vA1a; vC0b = vA0b; vC1b = vA1b;
            vD0a = vB0a; vD1a = vB1a; vD0b = vB0b; vD1b = vB1b;
        } else if (MODE == 1) {
            vC0a = vB0a; vC1a = vB1a; vC0b = vB0b; vC1b = vB1b;
            vD0a = ld_h4(fmt + (rows.z + c.x));
            vD1a = ld_h4(fmt + (rows.z + c.y));
            vD0b = ld_h4(fmt + (rows.z + c.z));
            vD1b = ld_h4(fmt + (rows.z + c.w));
        } else {
            vC0a = ld_h4(fmt + (rows.z + c.x));
            vC1a = ld_h4(fmt + (rows.z + c.y));
            vC0b = ld_h4(fmt + (rows.z + c.z));
            vC1b = ld_h4(fmt + (rows.z + c.w));
            vD0a = ld_h4(fmt + (rows.w + c.x));
            vD1a = ld_h4(fmt + (rows.w + c.y));
            vD0b = ld_h4(fmt + (rows.w + c.z));
            vD1b = ld_h4(fmt + (rows.w + c.w));
        }

        const h4 s_aa = quad4h(vA0a, vA1a, vB0a, vB1a,
                               as_h2(wAa.x), as_h2(wAa.y), as_h2(wAa.z), as_h2(wAa.w));
        const h4 s_ab = quad4h(vA0b, vA1b, vB0b, vB1b,
                               as_h2(wAb.x), as_h2(wAb.y), as_h2(wAb.z), as_h2(wAb.w));
        const h4 s_ba = quad4h(vC0a, vC1a, vD0a, vD1a,
                               as_h2(wBa.x), as_h2(wBa.y), as_h2(wBa.z), as_h2(wBa.w));
        const h4 s_bb = quad4h(vC0b, vC1b, vD0b, vD1b,
                               as_h2(wBb.x), as_h2(wBb.y), as_h2(wBb.z), as_h2(wBb.w));

        const h4 m = max4h(max4h(s_aa, s_ab), max4h(s_ba, s_bb));
        const float2 lo = __half22float2(m.a);
        const float2 hi = __half22float2(m.b);
        outp[px * 128] = make_float4(lo.x, lo.y, hi.x, hi.y);
    }
}

// One block per (pooled_row, roi). 128 threads x half4 = 512 channels.
__global__ __launch_bounds__(128) void roi_pool_kernel(
    float* __restrict__ out)          // [512,7,7,512]
{
    const int py  = blockIdx.x;       // 0..6
    const int roi = blockIdx.y;       // 0..511
    const int t   = threadIdx.x;      // channel group: c = 4*t

    const int rb   = roi * POOL + py;
    const int cb   = rb * POOL;
    const int4 rows = g_rows[rb];
    const int mode  = g_mode[rb];

    const uint2* fmt = (const uint2*)g_fmh + t;
    float4* outp = (float4*)out + (size_t)cb * 128 + t;

    const int4*  colsp = g_cols + cb;
    const uint4* waa   = g_waa + cb;
    const uint4* wab   = g_wab + cb;
    const uint4* wba   = g_wba + cb;
    const uint4* wbb   = g_wbb + cb;

    if (mode == 0)      run_row<0>(fmt, outp, colsp, waa, wab, wba, wbb, rows);
    else if (mode == 1) run_row<1>(fmt, outp, colsp, waa, wab, wba, wbb, rows);
    else                run_row<2>(fmt, outp, colsp, waa, wab, wba, wbb, rows);
}

extern "C" void kernel_launch(void* const* d_in, const int* in_sizes, int n_in,
                              void* d_out, int out_size)
{
    const float* fm   = (const float*)d_in[0];   // feature_maps [1,38,50,512]
    const float* rois = (const float*)d_in[1];   // [512,5]
    float* out = (float*)d_out;                  // [1,512,7,7,512]

    const int param_blocks = (N_CELLS + 255) / 256;          // 98
    prep_kernel<<<N8BLOCKS + param_blocks, 256>>>(fm, rois);

    dim3 grid(POOL, N_ROI);
    roi_pool_kernel<<<grid, 128>>>(out);
}